// round 9
// baseline (speedup 1.0000x reference)
#include <cuda_runtime.h>

#define Bn 8
#define Hn 512
#define Wn 512
#define HW (Hn*Wn)
#define NPIX (Bn*HW)
#define WPR 16                 // 32-px words per row
#define PW (NPIX/32)           // words per bit-plane = 65536
#define TR 16
#define HALO 7
#define RT (TR+2*HALO)         // 30 tile rows
#define ITEMS (RT*WPR)         // 480
#define NTH 512
#define NBLK (Bn*(Hn/TR))      // 256

// Bit-planes: 0-3 elem bits, 4-6 density bits, 7 grav, 8 fall
__device__ unsigned int g_bp[9 * PW];

__host__ __device__ constexpr unsigned long long make_den_lut() {
    constexpr int d[16] = {1,4,3,2,0,4,4,0,4,3,3,2,3,4,0,0};
    unsigned long long v = 0;
    for (int i = 0; i < 16; i++) v |= (unsigned long long)d[i] << (3*i);
    return v;
}
constexpr unsigned long long DEN_LUT = make_den_lut();
#define GRV_LUT 0x1E9Du

__device__ __forceinline__ unsigned eq_elem4(
    unsigned p0, unsigned p1, unsigned p2, unsigned p3, int E)
{
    unsigned b0 = (E & 1) ? p0 : ~p0;
    unsigned b1 = (E & 2) ? p1 : ~p1;
    unsigned b2 = (E & 4) ? p2 : ~p2;
    unsigned b3 = (E & 8) ? p3 : ~p3;
    return b0 & b1 & b2 & b3;
}

// ---------------------------------------------------------------------------
// Compress: warp = 128 consecutive pixels. Loads for TWO words (64 px/lane-
// pair batch) are hoisted ahead of the select/ballot logic for 26-deep MLP.
// Stone-gravity rule via word-shift of the above-row ch9 ballot mask.
// ---------------------------------------------------------------------------
__global__ void __launch_bounds__(256) k_compress(
    const float* __restrict__ world, const float* __restrict__ rnd,
    unsigned int* __restrict__ bp)
{
    int gt   = blockIdx.x * 256 + threadIdx.x;
    int gw   = gt >> 5;                       // warp id, 16384 total
    int lane = gt & 31;
    int pxb  = gw << 7;                       // 128 px per warp
    int b    = pxb >> 18;
    int off  = pxb & (HW - 1);
    int h    = off >> 9;
    int ws   = off & 511;                     // 0,128,256,384
    const float* row  = world + (size_t)b * 20 * HW + (size_t)h * Wn;
    const float* rrow = rnd   + (size_t)b * HW      + (size_t)h * Wn;
    const float* p9r  = world + (size_t)b * 20 * HW + (size_t)9 * HW
                      + (size_t)(h - 1) * Wn;   // only deref when h>0

    // above-row stone masks for all 4 words + edge carries
    unsigned m9a[4];
#pragma unroll
    for (int k = 0; k < 4; k++) {
        float a = (h > 0) ? p9r[ws + 32 * k + lane] : 0.f;
        m9a[k] = __ballot_sync(~0u, a > 0.5f);
    }
    unsigned cL = 0, cR = 0;
    if (h > 0 && ws > 0)        cL = (p9r[ws - 1]   > 0.5f) ? 1u : 0u;
    if (h > 0 && ws + 128 < Wn) cR = (p9r[ws + 128] > 0.5f) ? 1u : 0u;

#pragma unroll
    for (int kk = 0; kk < 4; kk += 2) {
        // ---- hoisted loads: 26 channel floats + 2 rand, all independent ----
        float v[13][2], r2[2];
#pragma unroll
        for (int c = 1; c < 14; c++) {
            const float* cp = row + (size_t)c * HW + ws + 32 * kk + lane;
            v[c - 1][0] = cp[0];
            v[c - 1][1] = cp[32];
        }
        r2[0] = rrow[ws + 32 * kk + lane];
        r2[1] = rrow[ws + 32 * kk + 32 + lane];

#pragma unroll
        for (int j = 0; j < 2; j++) {
            int k = kk + j;
            int e = 0;
#pragma unroll
            for (int c = 1; c < 14; c++)
                if (v[c - 1][j] > 0.5f) e = c;
            int den = (int)((DEN_LUT >> (3 * e)) & 7);
            int gvt = (GRV_LUT >> e) & 1;

            unsigned me0 = __ballot_sync(~0u, e & 1);
            unsigned me1 = __ballot_sync(~0u, e & 2);
            unsigned me2 = __ballot_sync(~0u, e & 4);
            unsigned me3 = __ballot_sync(~0u, e & 8);
            unsigned md0 = __ballot_sync(~0u, den & 1);
            unsigned md1 = __ballot_sync(~0u, den & 2);
            unsigned md2 = __ballot_sync(~0u, den & 4);
            unsigned mg  = __ballot_sync(~0u, gvt);
            unsigned mfa = __ballot_sync(~0u, r2[j] > 0.5f);

            unsigned stone = me0 & ~me1 & ~me2 & me3;     // e == 9
            unsigned lc = k ? (m9a[k - 1] >> 31) : cL;
            unsigned rc = (k < 3) ? (m9a[k + 1] & 1u) : cR;
            unsigned L = (m9a[k] << 1) | lc;
            unsigned R = (m9a[k] >> 1) | (rc << 31);
            unsigned gv = (mg & ~stone) | (stone & ~(L & R));

            unsigned w = me0;
            w = lane == 1 ? me1 : w;  w = lane == 2 ? me2 : w;
            w = lane == 3 ? me3 : w;  w = lane == 4 ? md0 : w;
            w = lane == 5 ? md1 : w;  w = lane == 6 ? md2 : w;
            w = lane == 7 ? gv  : w;  w = lane == 8 ? mfa : w;
            if (lane < 9) bp[lane * PW + gw * 4 + k] = w;
        }
    }
}

// ---------------------------------------------------------------------------
// Bitwise pass helpers (32 pixels per op)
// ---------------------------------------------------------------------------
__device__ __forceinline__ unsigned eq_den(const unsigned* p, int D) {
    unsigned b0 = (D & 1) ? p[4] : ~p[4];
    unsigned b1 = (D & 2) ? p[5] : ~p[5];
    unsigned b2 = (D & 4) ? p[6] : ~p[6];
    return b0 & b1 & b2;
}
__device__ __forceinline__ unsigned lt_den(const unsigned* p, int D) {
    if (D == 1) return ~p[6] & ~p[5] & ~p[4];
    if (D == 2) return ~p[6] & ~p[5];
    return ~p[6] & ~(p[5] & p[4]);              // D == 3
}
__device__ __forceinline__ unsigned gt3(
    unsigned x2, unsigned x1, unsigned x0,
    unsigned y2, unsigned y1, unsigned y0)
{
    unsigned eq2 = ~(x2 ^ y2), eq1 = ~(x1 ^ y1);
    return (x2 & ~y2) | (eq2 & x1 & ~y1) | (eq2 & eq1 & x0 & ~y0);
}

__shared__ unsigned s_mov[2][8][ITEMS];
__shared__ unsigned s_fall[ITEMS];
__shared__ unsigned s_dg[ITEMS];

template <int D>
__device__ __forceinline__ void grav_pass(
    unsigned (*src)[ITEMS], unsigned (*dst)[ITEMS], int i, int c)
{
    int rw = i * WPR + c;
    int ra = rw - WPR, rb = rw + WPR;
    unsigned s[8], a[8], bb[8];
#pragma unroll
    for (int p = 0; p < 8; p++) { s[p] = src[p][rw]; a[p] = src[p][ra]; bb[p] = src[p][rb]; }
    unsigned bel = eq_den(s, D) & lt_den(bb, D) & s[7] & bb[7];
    unsigned abv = eq_den(a, D) & lt_den(s, D) & a[7] & s[7];
    unsigned keep = ~(bel | abv);
#pragma unroll
    for (int p = 0; p < 8; p++)
        dst[p][rw] = (bel & bb[p]) | (abv & a[p]) | (keep & s[p]);
    s_dg[rw] |= abv;
}

template <int E, int LEFT>
__device__ __forceinline__ void diag_pass(
    unsigned (*src)[ITEMS], unsigned (*dst)[ITEMS], int i, int c)
{
    int rw = i * WPR + c;
    int wm = (c - 1) & 15, wp = (c + 1) & 15;
    int ba = (i - 1) * WPR, bbr = (i + 1) * WPR;

    unsigned s[8], bl[8], ar[8];
#pragma unroll
    for (int p = 0; p < 8; p++) s[p] = src[p][rw];
    unsigned sd = s_dg[rw], sf = s_fall[rw];
    unsigned bl_dg, ar_dg, ar_f;
    if (LEFT) {
#pragma unroll
        for (int p = 0; p < 8; p++) {
            bl[p] = __funnelshift_l(src[p][bbr + wm], src[p][bbr + c], 1);
            ar[p] = __funnelshift_r(src[p][ba + c], src[p][ba + wp], 1);
        }
        bl_dg = __funnelshift_l(s_dg[bbr + wm], s_dg[bbr + c], 1);
        ar_dg = __funnelshift_r(s_dg[ba + c], s_dg[ba + wp], 1);
        ar_f  = __funnelshift_r(s_fall[ba + c], s_fall[ba + wp], 1);
    } else {
#pragma unroll
        for (int p = 0; p < 8; p++) {
            bl[p] = __funnelshift_r(src[p][bbr + c], src[p][bbr + wp], 1);
            ar[p] = __funnelshift_l(src[p][ba + wm], src[p][ba + c], 1);
        }
        bl_dg = __funnelshift_r(s_dg[bbr + c], s_dg[bbr + wp], 1);
        ar_dg = __funnelshift_l(s_dg[ba + wm], s_dg[ba + c], 1);
        ar_f  = __funnelshift_l(s_fall[ba + wm], s_fall[ba + c], 1);
    }
    unsigned ms  = LEFT ? sf : ~sf;
    unsigned mar = LEFT ? ar_f : ~ar_f;
    unsigned bbl = eq_elem4(s[0], s[1], s[2], s[3], E) & ~bl_dg & ~sd & ms
                 & gt3(s[6], s[5], s[4], bl[6], bl[5], bl[4]) & s[7] & bl[7];
    unsigned bar = eq_elem4(ar[0], ar[1], ar[2], ar[3], E) & ~ar_dg & ~sd & mar
                 & gt3(ar[6], ar[5], ar[4], s[6], s[5], s[4]) & ar[7] & s[7];
    unsigned keep = ~(bbl | bar);
#pragma unroll
    for (int p = 0; p < 8; p++)
        dst[p][rw] = (bbl & bl[p]) | (bar & ar[p]) | (keep & s[p]);
}

// ---------------------------------------------------------------------------
// Fused sim (bit-sliced, shrinking ranges) + decompress to f32 world (R5).
// ---------------------------------------------------------------------------
__global__ void __launch_bounds__(NTH, 2) k_sim(
    const unsigned int* __restrict__ bp, float* __restrict__ out)
{
    int tid = threadIdx.x;
    int b = blockIdx.x >> 5, chunk = blockIdx.x & 31;
    int r0 = chunk * TR;

    // Load 9 planes (with vertical wrap) into SMEM
#pragma unroll
    for (int p = 0; p < 9; p++) {
        const unsigned* pp = bp + (size_t)p * PW + (size_t)b * (Hn * WPR);
        for (int rw = tid; rw < ITEMS; rw += NTH) {
            int i = rw >> 4, wq = rw & 15;
            int gr = (r0 - HALO + i) & (Hn - 1);
            unsigned v = pp[gr * WPR + wq];
            if (p < 8) s_mov[0][p][rw] = v; else s_fall[rw] = v;
        }
    }
    for (int rw = tid; rw < ITEMS; rw += NTH) s_dg[rw] = 0;
    __syncthreads();

    // Pass k computes exactly rows [k, RT-k)
    int i = (tid >> 4), c = tid & 15;
    if (tid < (RT- 2)*WPR) grav_pass<1>(s_mov[0], s_mov[1], i + 1, c);    __syncthreads();
    if (tid < (RT- 4)*WPR) grav_pass<2>(s_mov[1], s_mov[0], i + 2, c);    __syncthreads();
    if (tid < (RT- 6)*WPR) grav_pass<3>(s_mov[0], s_mov[1], i + 3, c);    __syncthreads();
    if (tid < (RT- 8)*WPR) diag_pass<2 ,1>(s_mov[1], s_mov[0], i + 4, c); __syncthreads();
    if (tid < (RT-10)*WPR) diag_pass<2 ,0>(s_mov[0], s_mov[1], i + 5, c); __syncthreads();
    if (tid < (RT-12)*WPR) diag_pass<12,1>(s_mov[1], s_mov[0], i + 6, c); __syncthreads();
    if (tid < (RT-14)*WPR) diag_pass<12,0>(s_mov[0], s_mov[1], i + 7, c); __syncthreads();
    // final state in s_mov[1], valid rows [HALO, HALO+TR)

    // Decompress valid rows to the 20-channel f32 world (R5-proven pattern)
    float* ob = out + (size_t)b * 20 * HW;
    for (int g2 = tid; g2 < TR * 128; g2 += NTH) {
        int ii = (g2 >> 7) + HALO;
        int q  = g2 & 127;                 // float4 group within row
        int wq = q >> 3;
        int k  = (q & 7) * 4;
        int rw = ii * WPR + wq;
        unsigned p0 = s_mov[1][0][rw], p1 = s_mov[1][1][rw];
        unsigned p2 = s_mov[1][2][rw], p3 = s_mov[1][3][rw];
        unsigned p4 = s_mov[1][4][rw], p5 = s_mov[1][5][rw];
        unsigned p6 = s_mov[1][6][rw], p7 = s_mov[1][7][rw];
        int e[4]; float dn[4], gv[4];
#pragma unroll
        for (int j = 0; j < 4; j++) {
            int kk = k + j;
            e[j] = ((p0 >> kk) & 1) | (((p1 >> kk) & 1) << 1)
                 | (((p2 >> kk) & 1) << 2) | (((p3 >> kk) & 1) << 3);
            dn[j] = (float)(((p4 >> kk) & 1) | (((p5 >> kk) & 1) << 1)
                          | (((p6 >> kk) & 1) << 2));
            gv[j] = (float)((p7 >> kk) & 1);
        }
        int gh = r0 + ii - HALO;
        float* op = ob + (size_t)gh * Wn + q * 4;
#pragma unroll
        for (int ch = 0; ch < 14; ch++) {
            float4 v = make_float4(e[0] == ch ? 1.f : 0.f, e[1] == ch ? 1.f : 0.f,
                                   e[2] == ch ? 1.f : 0.f, e[3] == ch ? 1.f : 0.f);
            *reinterpret_cast<float4*>(op + (size_t)ch * HW) = v;
        }
        *reinterpret_cast<float4*>(op + (size_t)14 * HW) =
            make_float4(dn[0], dn[1], dn[2], dn[3]);
        *reinterpret_cast<float4*>(op + (size_t)15 * HW) =
            make_float4(gv[0], gv[1], gv[2], gv[3]);
        float4 z = make_float4(0.f, 0.f, 0.f, 0.f);
#pragma unroll
        for (int ch = 16; ch < 20; ch++)
            *reinterpret_cast<float4*>(op + (size_t)ch * HW) = z;
    }
}

// ---------------------------------------------------------------------------
extern "C" void kernel_launch(void* const* d_in, const int* in_sizes, int n_in,
                              void* d_out, int out_size)
{
    int wi = 0, ri = 1;
    if (n_in >= 2 && in_sizes[0] < in_sizes[1]) { wi = 1; ri = 0; }
    const float* world = (const float*)d_in[wi];
    const float* rnd   = (const float*)d_in[ri];
    float* out = (float*)d_out;

    unsigned int* bp;
    cudaGetSymbolAddress((void**)&bp, g_bp);

    k_compress<<<(NPIX/4) / 256, 256>>>(world, rnd, bp);
    k_sim<<<NBLK, NTH>>>(bp, out);
}

// round 10
// speedup vs baseline: 1.1333x; 1.1333x over previous
#include <cuda_runtime.h>

#define Bn 8
#define Hn 512
#define Wn 512
#define HW (Hn*Wn)
#define NPIX (Bn*HW)
#define WPR 16                 // 32-px words per row
#define PW (NPIX/32)           // words per bit-plane = 65536
#define TR 16
#define HALO 7
#define RT (TR+2*HALO)         // 30 tile rows
#define ITEMS (RT*WPR)         // 480
#define NTH 512
#define NBLK (Bn*(Hn/TR))      // 256

// Bit-planes: 0-3 elem bits, 4-6 density bits, 7 grav, 8 fall
__device__ unsigned int g_bp[9 * PW];

__device__ __forceinline__ unsigned eq_elem4(
    unsigned p0, unsigned p1, unsigned p2, unsigned p3, int E)
{
    unsigned b0 = (E & 1) ? p0 : ~p0;
    unsigned b1 = (E & 2) ? p1 : ~p1;
    unsigned b2 = (E & 4) ? p2 : ~p2;
    unsigned b3 = (E & 8) ? p3 : ~p3;
    return b0 & b1 & b2 & b3;
}

// ---------------------------------------------------------------------------
// Compress (bitwise): warp = 128 contiguous px; lane owns 4 px (one uint4 per
// channel, coalesced). One-hot 0.0/1.0 floats -> bit 29 test (no FSETP).
// Plane nibbles = OR-trees of channel nibbles; stone rule via nibble shifts
// with shfl carries; 3-step shfl_xor OR-reduction packs nibbles into words.
// ---------------------------------------------------------------------------
__device__ __forceinline__ unsigned nib_of(uint4 u) {
    return ((u.x >> 29) & 1u) | (((u.y >> 29) & 1u) << 1)
         | (((u.z >> 29) & 1u) << 2) | (((u.w >> 29) & 1u) << 3);
}

__global__ void __launch_bounds__(256) k_compress(
    const float* __restrict__ world, const float* __restrict__ rnd,
    unsigned int* __restrict__ bp)
{
    int gt   = blockIdx.x * 256 + threadIdx.x;
    int gw   = gt >> 5;                       // warp id, 16384 total
    int lane = gt & 31;
    int pxb  = gw << 7;                       // 128 px per warp
    int b    = pxb >> 18;
    int off  = pxb & (HW - 1);
    int h    = off >> 9;
    int ws   = off & 511;                     // 0,128,256,384
    const float* row = world + (size_t)b * 20 * HW + (size_t)h * Wn;
    int lx = ws + 4 * lane;                   // this lane's first pixel col

    unsigned nb[14];                          // nb[c] for channels 1..13
#pragma unroll
    for (int c = 1; c < 14; c++)
        nb[c] = nib_of(*reinterpret_cast<const uint4*>(row + (size_t)c * HW + lx));

    // fall-direction nibble from rand (real compare; rand is uniform [0,1))
    float4 rv = *reinterpret_cast<const float4*>(
        rnd + (size_t)b * HW + (size_t)h * Wn + lx);
    unsigned nf = (rv.x > 0.5f ? 1u : 0u) | (rv.y > 0.5f ? 2u : 0u)
                | (rv.z > 0.5f ? 4u : 0u) | (rv.w > 0.5f ? 8u : 0u);

    // above-row stone nibble (zero-padded at absolute borders)
    const float* p9r = world + (size_t)b * 20 * HW + (size_t)9 * HW
                     + (size_t)(h - 1) * Wn;
    unsigned n9a = 0;
    if (h > 0) n9a = nib_of(*reinterpret_cast<const uint4*>(p9r + lx));
    unsigned prev = (__shfl_up_sync(~0u, n9a, 1) >> 3) & 1u;
    unsigned next = __shfl_down_sync(~0u, n9a, 1) & 1u;
    if (lane == 0)  prev = (h > 0 && ws > 0)        ? ((p9r[ws - 1]   > 0.5f) ? 1u : 0u) : 0u;
    if (lane == 31) next = (h > 0 && ws + 128 < Wn) ? ((p9r[ws + 128] > 0.5f) ? 1u : 0u) : 0u;
    unsigned Ln = ((n9a << 1) & 0xEu) | prev;     // stone at (px-1)
    unsigned Rn = (n9a >> 1) | (next << 3);       // stone at (px+1)

    // plane nibbles (OR lists from the element table)
    unsigned u13 = nb[1]|nb[2]|nb[3]|nb[4]|nb[5]|nb[6]|nb[7]
                 | nb[8]|nb[9]|nb[10]|nb[11]|nb[12]|nb[13];
    unsigned m0 = ~u13 & 0xFu;
    unsigned w0 = nb[1]|nb[3]|nb[5]|nb[7]|nb[9]|nb[11]|nb[13];        // elem bit0
    unsigned w1 = nb[2]|nb[3]|nb[6]|nb[7]|nb[10]|nb[11];              // elem bit1
    unsigned w2 = nb[4]|nb[5]|nb[6]|nb[7]|nb[12]|nb[13];              // elem bit2
    unsigned w3 = nb[8]|nb[9]|nb[10]|nb[11]|nb[12]|nb[13];            // elem bit3
    unsigned w4 = m0|nb[2]|nb[9]|nb[10]|nb[12];                       // den bit0
    unsigned w5 = nb[2]|nb[3]|nb[9]|nb[10]|nb[11]|nb[12];             // den bit1
    unsigned w6 = nb[1]|nb[5]|nb[6]|nb[8]|nb[13];                     // den bit2
    unsigned w7 = m0|nb[2]|nb[3]|nb[4]|nb[7]|nb[10]|nb[11]|nb[12]     // grav
                | (nb[9] & ~(Ln & Rn));
    unsigned w8 = nf;                                                 // fall

    // pack: nibble -> word per 8-lane group, via butterfly OR-reduce
    int sh = (lane & 7) * 4;
    unsigned v0 = w0 << sh, v1 = w1 << sh, v2 = w2 << sh, v3 = w3 << sh;
    unsigned v4 = w4 << sh, v5 = w5 << sh, v6 = w6 << sh, v7 = w7 << sh;
    unsigned v8 = w8 << sh;
#pragma unroll
    for (int s = 1; s < 8; s <<= 1) {
        v0 |= __shfl_xor_sync(~0u, v0, s);
        v1 |= __shfl_xor_sync(~0u, v1, s);
        v2 |= __shfl_xor_sync(~0u, v2, s);
        v3 |= __shfl_xor_sync(~0u, v3, s);
        v4 |= __shfl_xor_sync(~0u, v4, s);
        v5 |= __shfl_xor_sync(~0u, v5, s);
        v6 |= __shfl_xor_sync(~0u, v6, s);
        v7 |= __shfl_xor_sync(~0u, v7, s);
        v8 |= __shfl_xor_sync(~0u, v8, s);
    }
    int idx = gw * 4 + (lane >> 3);           // global word index
    int sel = lane & 7;
    unsigned sv = v0;
    sv = sel == 1 ? v1 : sv;  sv = sel == 2 ? v2 : sv;
    sv = sel == 3 ? v3 : sv;  sv = sel == 4 ? v4 : sv;
    sv = sel == 5 ? v5 : sv;  sv = sel == 6 ? v6 : sv;
    sv = sel == 7 ? v7 : sv;
    bp[sel * PW + idx] = sv;
    if (sel == 0) bp[8 * PW + idx] = v8;
}

// ---------------------------------------------------------------------------
// Bitwise pass helpers (32 pixels per op)
// ---------------------------------------------------------------------------
__device__ __forceinline__ unsigned eq_den(const unsigned* p, int D) {
    unsigned b0 = (D & 1) ? p[4] : ~p[4];
    unsigned b1 = (D & 2) ? p[5] : ~p[5];
    unsigned b2 = (D & 4) ? p[6] : ~p[6];
    return b0 & b1 & b2;
}
__device__ __forceinline__ unsigned lt_den(const unsigned* p, int D) {
    if (D == 1) return ~p[6] & ~p[5] & ~p[4];
    if (D == 2) return ~p[6] & ~p[5];
    return ~p[6] & ~(p[5] & p[4]);              // D == 3
}
__device__ __forceinline__ unsigned gt3(
    unsigned x2, unsigned x1, unsigned x0,
    unsigned y2, unsigned y1, unsigned y0)
{
    unsigned eq2 = ~(x2 ^ y2), eq1 = ~(x1 ^ y1);
    return (x2 & ~y2) | (eq2 & x1 & ~y1) | (eq2 & eq1 & x0 & ~y0);
}

__shared__ unsigned s_mov[2][8][ITEMS];
__shared__ unsigned s_fall[ITEMS];
__shared__ unsigned s_dg[ITEMS];

template <int D>
__device__ __forceinline__ void grav_pass(
    unsigned (*src)[ITEMS], unsigned (*dst)[ITEMS], int i, int c)
{
    int rw = i * WPR + c;
    int ra = rw - WPR, rb = rw + WPR;
    unsigned s[8], a[8], bb[8];
#pragma unroll
    for (int p = 0; p < 8; p++) { s[p] = src[p][rw]; a[p] = src[p][ra]; bb[p] = src[p][rb]; }
    unsigned bel = eq_den(s, D) & lt_den(bb, D) & s[7] & bb[7];
    unsigned abv = eq_den(a, D) & lt_den(s, D) & a[7] & s[7];
    unsigned keep = ~(bel | abv);
#pragma unroll
    for (int p = 0; p < 8; p++)
        dst[p][rw] = (bel & bb[p]) | (abv & a[p]) | (keep & s[p]);
    s_dg[rw] |= abv;
}

template <int E, int LEFT>
__device__ __forceinline__ void diag_pass(
    unsigned (*src)[ITEMS], unsigned (*dst)[ITEMS], int i, int c)
{
    int rw = i * WPR + c;
    int wm = (c - 1) & 15, wp = (c + 1) & 15;
    int ba = (i - 1) * WPR, bbr = (i + 1) * WPR;

    unsigned s[8], bl[8], ar[8];
#pragma unroll
    for (int p = 0; p < 8; p++) s[p] = src[p][rw];
    unsigned sd = s_dg[rw], sf = s_fall[rw];
    unsigned bl_dg, ar_dg, ar_f;
    if (LEFT) {
#pragma unroll
        for (int p = 0; p < 8; p++) {
            bl[p] = __funnelshift_l(src[p][bbr + wm], src[p][bbr + c], 1);
            ar[p] = __funnelshift_r(src[p][ba + c], src[p][ba + wp], 1);
        }
        bl_dg = __funnelshift_l(s_dg[bbr + wm], s_dg[bbr + c], 1);
        ar_dg = __funnelshift_r(s_dg[ba + c], s_dg[ba + wp], 1);
        ar_f  = __funnelshift_r(s_fall[ba + c], s_fall[ba + wp], 1);
    } else {
#pragma unroll
        for (int p = 0; p < 8; p++) {
            bl[p] = __funnelshift_r(src[p][bbr + c], src[p][bbr + wp], 1);
            ar[p] = __funnelshift_l(src[p][ba + wm], src[p][ba + c], 1);
        }
        bl_dg = __funnelshift_r(s_dg[bbr + c], s_dg[bbr + wp], 1);
        ar_dg = __funnelshift_l(s_dg[ba + wm], s_dg[ba + c], 1);
        ar_f  = __funnelshift_l(s_fall[ba + wm], s_fall[ba + c], 1);
    }
    unsigned ms  = LEFT ? sf : ~sf;
    unsigned mar = LEFT ? ar_f : ~ar_f;
    unsigned bbl = eq_elem4(s[0], s[1], s[2], s[3], E) & ~bl_dg & ~sd & ms
                 & gt3(s[6], s[5], s[4], bl[6], bl[5], bl[4]) & s[7] & bl[7];
    unsigned bar = eq_elem4(ar[0], ar[1], ar[2], ar[3], E) & ~ar_dg & ~sd & mar
                 & gt3(ar[6], ar[5], ar[4], s[6], s[5], s[4]) & ar[7] & s[7];
    unsigned keep = ~(bbl | bar);
#pragma unroll
    for (int p = 0; p < 8; p++)
        dst[p][rw] = (bbl & bl[p]) | (bar & ar[p]) | (keep & s[p]);
}

// ---------------------------------------------------------------------------
// Fused sim (bit-sliced, shrinking ranges) + decompress to f32 world.
// ---------------------------------------------------------------------------
__global__ void __launch_bounds__(NTH, 2) k_sim(
    const unsigned int* __restrict__ bp, float* __restrict__ out)
{
    int tid = threadIdx.x;
    int b = blockIdx.x >> 5, chunk = blockIdx.x & 31;
    int r0 = chunk * TR;

#pragma unroll
    for (int p = 0; p < 9; p++) {
        const unsigned* pp = bp + (size_t)p * PW + (size_t)b * (Hn * WPR);
        for (int rw = tid; rw < ITEMS; rw += NTH) {
            int i = rw >> 4, wq = rw & 15;
            int gr = (r0 - HALO + i) & (Hn - 1);
            unsigned v = pp[gr * WPR + wq];
            if (p < 8) s_mov[0][p][rw] = v; else s_fall[rw] = v;
        }
    }
    for (int rw = tid; rw < ITEMS; rw += NTH) s_dg[rw] = 0;
    __syncthreads();

    // Pass k computes exactly rows [k, RT-k)
    int i = (tid >> 4), c = tid & 15;
    if (tid < (RT- 2)*WPR) grav_pass<1>(s_mov[0], s_mov[1], i + 1, c);    __syncthreads();
    if (tid < (RT- 4)*WPR) grav_pass<2>(s_mov[1], s_mov[0], i + 2, c);    __syncthreads();
    if (tid < (RT- 6)*WPR) grav_pass<3>(s_mov[0], s_mov[1], i + 3, c);    __syncthreads();
    if (tid < (RT- 8)*WPR) diag_pass<2 ,1>(s_mov[1], s_mov[0], i + 4, c); __syncthreads();
    if (tid < (RT-10)*WPR) diag_pass<2 ,0>(s_mov[0], s_mov[1], i + 5, c); __syncthreads();
    if (tid < (RT-12)*WPR) diag_pass<12,1>(s_mov[1], s_mov[0], i + 6, c); __syncthreads();
    if (tid < (RT-14)*WPR) diag_pass<12,0>(s_mov[0], s_mov[1], i + 7, c); __syncthreads();
    // final state in s_mov[1], valid rows [HALO, HALO+TR)

    // Decompress valid rows to the 20-channel f32 world
    float* ob = out + (size_t)b * 20 * HW;
    for (int g2 = tid; g2 < TR * 128; g2 += NTH) {
        int ii = (g2 >> 7) + HALO;
        int q  = g2 & 127;                 // float4 group within row
        int wq = q >> 3;
        int k  = (q & 7) * 4;
        int rw = ii * WPR + wq;
        unsigned p0 = s_mov[1][0][rw], p1 = s_mov[1][1][rw];
        unsigned p2 = s_mov[1][2][rw], p3 = s_mov[1][3][rw];
        unsigned p4 = s_mov[1][4][rw], p5 = s_mov[1][5][rw];
        unsigned p6 = s_mov[1][6][rw], p7 = s_mov[1][7][rw];
        int e[4]; float dn[4], gv[4];
#pragma unroll
        for (int j = 0; j < 4; j++) {
            int kk = k + j;
            e[j] = ((p0 >> kk) & 1) | (((p1 >> kk) & 1) << 1)
                 | (((p2 >> kk) & 1) << 2) | (((p3 >> kk) & 1) << 3);
            dn[j] = (float)(((p4 >> kk) & 1) | (((p5 >> kk) & 1) << 1)
                          | (((p6 >> kk) & 1) << 2));
            gv[j] = (float)((p7 >> kk) & 1);
        }
        int gh = r0 + ii - HALO;
        float* op = ob + (size_t)gh * Wn + q * 4;
#pragma unroll
        for (int ch = 0; ch < 14; ch++) {
            float4 v = make_float4(e[0] == ch ? 1.f : 0.f, e[1] == ch ? 1.f : 0.f,
                                   e[2] == ch ? 1.f : 0.f, e[3] == ch ? 1.f : 0.f);
            *reinterpret_cast<float4*>(op + (size_t)ch * HW) = v;
        }
        *reinterpret_cast<float4*>(op + (size_t)14 * HW) =
            make_float4(dn[0], dn[1], dn[2], dn[3]);
        *reinterpret_cast<float4*>(op + (size_t)15 * HW) =
            make_float4(gv[0], gv[1], gv[2], gv[3]);
        float4 z = make_float4(0.f, 0.f, 0.f, 0.f);
#pragma unroll
        for (int ch = 16; ch < 20; ch++)
            *reinterpret_cast<float4*>(op + (size_t)ch * HW) = z;
    }
}

// ---------------------------------------------------------------------------
extern "C" void kernel_launch(void* const* d_in, const int* in_sizes, int n_in,
                              void* d_out, int out_size)
{
    int wi = 0, ri = 1;
    if (n_in >= 2 && in_sizes[0] < in_sizes[1]) { wi = 1; ri = 0; }
    const float* world = (const float*)d_in[wi];
    const float* rnd   = (const float*)d_in[ri];
    float* out = (float*)d_out;

    unsigned int* bp;
    cudaGetSymbolAddress((void**)&bp, g_bp);

    k_compress<<<(NPIX/4) / 256, 256>>>(world, rnd, bp);
    k_sim<<<NBLK, NTH>>>(bp, out);
}